// round 1
// baseline (speedup 1.0000x reference)
#include <cuda_runtime.h>
#include <math.h>

// Problem constants
#define Bn    8
#define Tn    2048
#define Dn    1024
#define DSn   256
#define KLn   32
#define WINn  3
// SCALE = sqrt(DS) = 16

// Scratch for Q and K projections (16384 x 256 fp32 each = 16 MB each)
__device__ float g_Q[Bn * Tn * DSn];
__device__ float g_K[Bn * Tn * DSn];

// ----------------------------------------------------------------------------
// Stage 1: Q = X @ W_Q, K = X @ W_K  fused as X(16384x1024) @ [W_Q|W_K](1024x512)
// Classic 128x128x8 SGEMM, 8x8 microtiles, 256 threads.
// grid = (4 col-blocks, 128 row-blocks)
// ----------------------------------------------------------------------------
__global__ __launch_bounds__(256, 1)
void qk_gemm_kernel(const float* __restrict__ X,
                    const float* __restrict__ WQ,
                    const float* __restrict__ WK)
{
    constexpr int BM = 128, BN = 128, BK = 8;
    __shared__ float As[BK][BM + 4];   // +4 pad kills STS bank conflicts
    __shared__ float Bs[BK][BN];

    const int tid  = threadIdx.x;
    const int nblk = blockIdx.x;               // 0..3 : 0,1 -> W_Q ; 2,3 -> W_K
    const int mblk = blockIdx.y;               // 0..127

    const float* W      = (nblk < 2) ? WQ : WK;
    float*       Cout   = (nblk < 2) ? g_Q : g_K;
    const int    coloff = (nblk & 1) * 128;

    const float* A = X + (size_t)mblk * BM * Dn;

    // A-tile load map: 1 float4 / thread (128 rows x 8 cols)
    const int aRow = tid >> 1;            // 0..127
    const int aCol = (tid & 1) * 4;       // 0 or 4
    // B-tile load map: 1 float4 / thread (8 rows x 128 cols)
    const int bRow = tid >> 5;            // 0..7
    const int bCol = (tid & 31) * 4;      // 0..124

    const int tr = tid >> 4;              // 0..15  (rows of microtile grid)
    const int tc = tid & 15;              // 0..15  (cols)

    float acc[8][8];
#pragma unroll
    for (int i = 0; i < 8; i++)
#pragma unroll
        for (int j = 0; j < 8; j++) acc[i][j] = 0.f;

    for (int kt = 0; kt < Dn; kt += BK) {
        float4 av = *(const float4*)(A + (size_t)aRow * Dn + kt + aCol);
        As[aCol + 0][aRow] = av.x;
        As[aCol + 1][aRow] = av.y;
        As[aCol + 2][aRow] = av.z;
        As[aCol + 3][aRow] = av.w;

        float4 bv = *(const float4*)(W + (size_t)(kt + bRow) * DSn + coloff + bCol);
        *(float4*)&Bs[bRow][bCol] = bv;

        __syncthreads();

#pragma unroll
        for (int k = 0; k < BK; k++) {
            float rm[8], rn[8];
            float4 m0 = *(const float4*)&As[k][tr * 8];
            float4 m1 = *(const float4*)&As[k][tr * 8 + 4];
            rm[0]=m0.x; rm[1]=m0.y; rm[2]=m0.z; rm[3]=m0.w;
            rm[4]=m1.x; rm[5]=m1.y; rm[6]=m1.z; rm[7]=m1.w;
            float4 n0 = *(const float4*)&Bs[k][tc * 8];
            float4 n1 = *(const float4*)&Bs[k][tc * 8 + 4];
            rn[0]=n0.x; rn[1]=n0.y; rn[2]=n0.z; rn[3]=n0.w;
            rn[4]=n1.x; rn[5]=n1.y; rn[6]=n1.z; rn[7]=n1.w;
#pragma unroll
            for (int i = 0; i < 8; i++)
#pragma unroll
                for (int j = 0; j < 8; j++)
                    acc[i][j] = fmaf(rm[i], rn[j], acc[i][j]);
        }
        __syncthreads();
    }

    // Write back: 2 float4 per microtile row. Dest row stride = DS = 256.
#pragma unroll
    for (int i = 0; i < 8; i++) {
        const int grow = mblk * BM + tr * 8 + i;
        float* dst = Cout + (size_t)grow * DSn + coloff + tc * 8;
        float4 v0 = make_float4(acc[i][0], acc[i][1], acc[i][2], acc[i][3]);
        float4 v1 = make_float4(acc[i][4], acc[i][5], acc[i][6], acc[i][7]);
        *(float4*)dst       = v0;
        *(float4*)(dst + 4) = v1;
    }
}

// ----------------------------------------------------------------------------
// Stage 2: banded attention + ctx + projection + softmax, fused.
// One warp per query position t. 8 warps (8 t's) per block share smem ctx.
// grid = (T/8, B), block = 256
// ----------------------------------------------------------------------------
__global__ __launch_bounds__(256)
void ctx_proj_kernel(const float* __restrict__ h,
                     const float* __restrict__ tau,
                     const float* __restrict__ Wp,
                     float* __restrict__ out)
{
    __shared__ float ctx_sh[8 * Dn];   // 32 KB

    const int b    = blockIdx.y;
    const int t0   = blockIdx.x * 8;
    const int w    = threadIdx.x >> 5;
    const int lane = threadIdx.x & 31;
    const int t    = t0 + w;

    // ---- banded scores: Q[t] . K[s], s in [t-3, t+3] ----
    const float* Qt = g_Q + ((size_t)(b * Tn + t)) * DSn + lane * 8;
    const float4 q0 = *(const float4*)(Qt);
    const float4 q1 = *(const float4*)(Qt + 4);

    float a[7];
#pragma unroll
    for (int i = 0; i < 7; i++) {
        const int s  = t - WINn + i;
        const int sc = min(max(s, 0), Tn - 1);     // clamped (safe) address
        const float* Ks = g_K + ((size_t)(b * Tn + sc)) * DSn + lane * 8;
        const float4 k0 = *(const float4*)(Ks);
        const float4 k1 = *(const float4*)(Ks + 4);
        float p = q0.x*k0.x + q0.y*k0.y + q0.z*k0.z + q0.w*k0.w
                + q1.x*k1.x + q1.y*k1.y + q1.z*k1.z + q1.w*k1.w;
#pragma unroll
        for (int off = 16; off; off >>= 1)
            p += __shfl_xor_sync(0xffffffffu, p, off);
        a[i] = (s >= 0 && s < Tn) ? p * (1.0f / 16.0f) : -INFINITY;
    }

    // softmax over the (<=7) valid band entries
    float m = a[0];
#pragma unroll
    for (int i = 1; i < 7; i++) m = fmaxf(m, a[i]);
    float sum = 0.f;
#pragma unroll
    for (int i = 0; i < 7; i++) { a[i] = expf(a[i] - m); sum += a[i]; }
    const float inv = 1.0f / sum;
#pragma unroll
    for (int i = 0; i < 7; i++) a[i] *= inv;   // invalid -> exp(-inf)=0

    // ---- ctx[t] = sum_s a_s * h[b][s][:]  -> smem ----
    const float* hb = h + (size_t)b * Tn * Dn;
#pragma unroll
    for (int j = 0; j < 8; j++) {
        const int dbase = (lane + 32 * j) * 4;   // float4 index into D
        float4 accv = make_float4(0.f, 0.f, 0.f, 0.f);
#pragma unroll
        for (int i = 0; i < 7; i++) {
            const int sc = min(max(t - WINn + i, 0), Tn - 1);
            const float4 hv = *(const float4*)(hb + (size_t)sc * Dn + dbase);
            accv.x = fmaf(a[i], hv.x, accv.x);
            accv.y = fmaf(a[i], hv.y, accv.y);
            accv.z = fmaf(a[i], hv.z, accv.z);
            accv.w = fmaf(a[i], hv.w, accv.w);
        }
        *(float4*)&ctx_sh[w * Dn + dbase] = accv;
    }
    __syncthreads();

    // ---- logits[t][k] = (ctx[t] . W_proj[:,k]) / tau ; softmax over k ----
    const int tl = w;          // this warp now owns logits for t = t0 + tl
    const int k  = lane;       // class index
    const float* crow = ctx_sh + tl * Dn;

    float accl = 0.f;
#pragma unroll 8
    for (int d = 0; d < Dn; d += 4) {
        const float4 cv = *(const float4*)(crow + d);
        accl = fmaf(cv.x, Wp[(d + 0) * KLn + k], accl);
        accl = fmaf(cv.y, Wp[(d + 1) * KLn + k], accl);
        accl = fmaf(cv.z, Wp[(d + 2) * KLn + k], accl);
        accl = fmaf(cv.w, Wp[(d + 3) * KLn + k], accl);
    }
    const float logit = accl / tau[0];

    float mm = logit;
#pragma unroll
    for (int off = 16; off; off >>= 1)
        mm = fmaxf(mm, __shfl_xor_sync(0xffffffffu, mm, off));
    const float e = expf(logit - mm);
    float ss = e;
#pragma unroll
    for (int off = 16; off; off >>= 1)
        ss += __shfl_xor_sync(0xffffffffu, ss, off);

    out[((size_t)(b * Tn + t)) * KLn + k] = e / ss;
}

// ----------------------------------------------------------------------------
// Launch
// inputs (metadata order): h_base, tau, W_Q, W_K, W_proj ; output float32
// ----------------------------------------------------------------------------
extern "C" void kernel_launch(void* const* d_in, const int* in_sizes, int n_in,
                              void* d_out, int out_size)
{
    const float* h   = (const float*)d_in[0];
    const float* tau = (const float*)d_in[1];
    const float* WQ  = (const float*)d_in[2];
    const float* WK  = (const float*)d_in[3];
    const float* Wp  = (const float*)d_in[4];
    float* out = (float*)d_out;

    dim3 g1(4, (Bn * Tn) / 128);          // (512/128 col-blocks, 16384/128 row-blocks)
    qk_gemm_kernel<<<g1, 256>>>(h, WQ, WK);

    dim3 g2(Tn / 8, Bn);
    ctx_proj_kernel<<<g2, 256>>>(h, tau, Wp, out);
}

// round 5
// speedup vs baseline: 1.7460x; 1.7460x over previous
#include <cuda_runtime.h>
#include <cuda_bf16.h>
#include <math.h>
#include <stdint.h>

// Problem constants
#define Bn    8
#define Tn    2048
#define Dn    1024
#define DSn   256
#define KLn   32
#define WINn  3
#define Mtot  (Bn * Tn)      // 16384
// SCALE = sqrt(DS) = 16

// Scratch
__device__ float g_Q[Mtot * DSn];                    // 16 MB
__device__ float g_K[Mtot * DSn];                    // 16 MB
__device__ __nv_bfloat16 g_Xhi[Mtot * Dn];           // 32 MB
__device__ __nv_bfloat16 g_Xlo[Mtot * Dn];           // 32 MB
#define KTOT 3072
__device__ __nv_bfloat16 g_Wsp[512 * KTOT];          // 3 MB: [n][k''], k''=[hi|lo|hi]

__device__ __forceinline__ uint32_t smem_u32(const void* p) {
    uint32_t a;
    asm("{ .reg .u64 t; cvta.to.shared.u64 t, %1; cvt.u32.u64 %0, t; }" : "=r"(a) : "l"(p));
    return a;
}

// ---------------------------------------------------------------------------
// Convert X (fp32) -> bf16 hi/lo
// ---------------------------------------------------------------------------
__global__ void convert_x_kernel(const float* __restrict__ X) {
    int idx = blockIdx.x * blockDim.x + threadIdx.x;     // float4 index
    float4 v = *(const float4*)(X + (size_t)idx * 4);
    __nv_bfloat16 hx = __float2bfloat16(v.x);
    __nv_bfloat16 hy = __float2bfloat16(v.y);
    __nv_bfloat16 hz = __float2bfloat16(v.z);
    __nv_bfloat16 hw = __float2bfloat16(v.w);
    __nv_bfloat162 hp0(hx, hy), hp1(hz, hw);
    __nv_bfloat162 lp0(__float2bfloat16(v.x - __bfloat162float(hx)),
                       __float2bfloat16(v.y - __bfloat162float(hy)));
    __nv_bfloat162 lp1(__float2bfloat16(v.z - __bfloat162float(hz)),
                       __float2bfloat16(v.w - __bfloat162float(hw)));
    *(uint2*)(g_Xhi + (size_t)idx * 4) = make_uint2(*(uint32_t*)&hp0, *(uint32_t*)&hp1);
    *(uint2*)(g_Xlo + (size_t)idx * 4) = make_uint2(*(uint32_t*)&lp0, *(uint32_t*)&lp1);
}

// ---------------------------------------------------------------------------
// Build B'' = [Whi | Wlo | Whi] transposed to [n][k''] (n<256: WQ, else WK)
// ---------------------------------------------------------------------------
__global__ void convert_w_kernel(const float* __restrict__ WQ, const float* __restrict__ WK) {
    int idx = blockIdx.x * blockDim.x + threadIdx.x;     // 0 .. 512*3072-1
    int n  = idx / KTOT;
    int kk = idx - n * KTOT;
    int reg = kk >> 10;            // 0:hi 1:lo 2:hi
    int k   = kk & 1023;
    float x = (n < 256) ? WQ[k * 256 + n] : WK[k * 256 + (n - 256)];
    __nv_bfloat16 hi = __float2bfloat16(x);
    __nv_bfloat16 outv = (reg == 1) ? __float2bfloat16(x - __bfloat162float(hi)) : hi;
    g_Wsp[idx] = outv;
}

// ---------------------------------------------------------------------------
// bf16 mma.sync GEMM: [Q|K](16384 x 512) over K''=3072 (3xBF16 fp32 emulation)
// CTA tile 128x128, BK=64. 8 warps: 2(M) x 4(N), warp tile 64x32.
// ---------------------------------------------------------------------------
#define BM 128
#define BN 128
#define BK 64
#define PAD 8
#define LDS_A (BK + PAD)    // 72 bf16 = 144 B row stride (16B-aligned, ldmatrix conflict-free)

__global__ __launch_bounds__(256, 2)
void qk_mma_kernel() {
    __shared__ __nv_bfloat16 As[BM * LDS_A];
    __shared__ __nv_bfloat16 Bs[BN * LDS_A];

    const int tid  = threadIdx.x;
    const int wid  = tid >> 5;
    const int lane = tid & 31;
    const int wm = wid & 1;            // 0..1  -> m base
    const int wn = wid >> 1;           // 0..3  -> n base
    const int mbase = wm * 64;
    const int nbase = wn * 32;
    const int mtile = blockIdx.y * BM;
    const int ntile = blockIdx.x * BN;

    const int g = lane >> 3;           // ldmatrix group 0..3
    const int r = lane & 7;

    float d[4][4][4];
#pragma unroll
    for (int i = 0; i < 4; i++)
#pragma unroll
        for (int j = 0; j < 4; j++)
#pragma unroll
            for (int q = 0; q < 4; q++) d[i][j][q] = 0.f;

    const uint32_t as_base = smem_u32(As);
    const uint32_t bs_base = smem_u32(Bs);

    for (int it = 0; it < KTOT / BK; it++) {
        const int kb = it * BK;
        // ---- A tile: 128 rows x 64 bf16 from Xhi (k''<2048) or Xlo ----
        const __nv_bfloat16* Asrc = (kb < 2048) ? g_Xhi : g_Xlo;
        const int ksrc = kb & 1023;
#pragma unroll
        for (int i = 0; i < 4; i++) {
            int idx = i * 256 + tid;               // 0..1023 uint4 slots
            int row = idx >> 3;
            int c8  = (idx & 7) * 8;
            uint4 v = *(const uint4*)(Asrc + (size_t)(mtile + row) * Dn + ksrc + c8);
            *(uint4*)(As + row * LDS_A + c8) = v;
        }
        // ---- B tile: 128 n-rows x 64 bf16 from prebuilt Wsp ----
#pragma unroll
        for (int i = 0; i < 4; i++) {
            int idx = i * 256 + tid;
            int row = idx >> 3;
            int c8  = (idx & 7) * 8;
            uint4 v = *(const uint4*)(g_Wsp + (size_t)(ntile + row) * KTOT + kb + c8);
            *(uint4*)(Bs + row * LDS_A + c8) = v;
        }
        __syncthreads();

#pragma unroll
        for (int ks = 0; ks < BK / 16; ks++) {
            const int k0 = ks * 16;
            uint32_t a[4][4];
#pragma unroll
            for (int mf = 0; mf < 4; mf++) {
                int row = mbase + mf * 16 + (g & 1) * 8 + r;
                int col = k0 + (g >> 1) * 8;
                uint32_t addr = as_base + (uint32_t)(row * LDS_A + col) * 2u;
                asm volatile("ldmatrix.sync.aligned.m8n8.x4.shared.b16 {%0,%1,%2,%3}, [%4];"
                             : "=r"(a[mf][0]), "=r"(a[mf][1]), "=r"(a[mf][2]), "=r"(a[mf][3])
                             : "r"(addr));
            }
            uint32_t b[4][2];
#pragma unroll
            for (int nh = 0; nh < 2; nh++) {
                int row = nbase + nh * 16 + (g >> 1) * 8 + r;
                int col = k0 + (g & 1) * 8;
                uint32_t addr = bs_base + (uint32_t)(row * LDS_A + col) * 2u;
                uint32_t t0, t1, t2, t3;
                asm volatile("ldmatrix.sync.aligned.m8n8.x4.shared.b16 {%0,%1,%2,%3}, [%4];"
                             : "=r"(t0), "=r"(t1), "=r"(t2), "=r"(t3) : "r"(addr));
                b[nh * 2 + 0][0] = t0; b[nh * 2 + 0][1] = t1;
                b[nh * 2 + 1][0] = t2; b[nh * 2 + 1][1] = t3;
            }
#pragma unroll
            for (int mf = 0; mf < 4; mf++)
#pragma unroll
                for (int nf = 0; nf < 4; nf++) {
                    asm volatile(
                        "mma.sync.aligned.m16n8k16.row.col.f32.bf16.bf16.f32 "
                        "{%0,%1,%2,%3}, {%4,%5,%6,%7}, {%8,%9}, {%0,%1,%2,%3};"
                        : "+f"(d[mf][nf][0]), "+f"(d[mf][nf][1]),
                          "+f"(d[mf][nf][2]), "+f"(d[mf][nf][3])
                        : "r"(a[mf][0]), "r"(a[mf][1]), "r"(a[mf][2]), "r"(a[mf][3]),
                          "r"(b[nf][0]), "r"(b[nf][1]));
                }
        }
        __syncthreads();
    }

    // ---- Epilogue: ntile<256 -> Q, else K (BN=128 keeps tiles on one side) ----
    float* dst = (ntile < 256) ? g_Q : g_K;
    const int ncol0 = (ntile & 255) + nbase;
#pragma unroll
    for (int mf = 0; mf < 4; mf++) {
#pragma unroll
        for (int nf = 0; nf < 4; nf++) {
            int row = mtile + mbase + mf * 16 + (lane >> 2);
            int col = ncol0 + nf * 8 + (lane & 3) * 2;
            *(float2*)(dst + (size_t)row * DSn + col) =
                make_float2(d[mf][nf][0], d[mf][nf][1]);
            *(float2*)(dst + (size_t)(row + 8) * DSn + col) =
                make_float2(d[mf][nf][2], d[mf][nf][3]);
        }
    }
}

// ----------------------------------------------------------------------------
// Stage 2: banded attention + ctx + projection + softmax, fused (unchanged).
// ----------------------------------------------------------------------------
__global__ __launch_bounds__(256)
void ctx_proj_kernel(const float* __restrict__ h,
                     const float* __restrict__ tau,
                     const float* __restrict__ Wp,
                     float* __restrict__ out)
{
    __shared__ float ctx_sh[8 * Dn];   // 32 KB

    const int b    = blockIdx.y;
    const int t0   = blockIdx.x * 8;
    const int w    = threadIdx.x >> 5;
    const int lane = threadIdx.x & 31;
    const int t    = t0 + w;

    const float* Qt = g_Q + ((size_t)(b * Tn + t)) * DSn + lane * 8;
    const float4 q0 = *(const float4*)(Qt);
    const float4 q1 = *(const float4*)(Qt + 4);

    float a[7];
#pragma unroll
    for (int i = 0; i < 7; i++) {
        const int s  = t - WINn + i;
        const int sc = min(max(s, 0), Tn - 1);
        const float* Ks = g_K + ((size_t)(b * Tn + sc)) * DSn + lane * 8;
        const float4 k0 = *(const float4*)(Ks);
        const float4 k1 = *(const float4*)(Ks + 4);
        float p = q0.x*k0.x + q0.y*k0.y + q0.z*k0.z + q0.w*k0.w
                + q1.x*k1.x + q1.y*k1.y + q1.z*k1.z + q1.w*k1.w;
#pragma unroll
        for (int off = 16; off; off >>= 1)
            p += __shfl_xor_sync(0xffffffffu, p, off);
        a[i] = (s >= 0 && s < Tn) ? p * (1.0f / 16.0f) : -INFINITY;
    }

    float m = a[0];
#pragma unroll
    for (int i = 1; i < 7; i++) m = fmaxf(m, a[i]);
    float sum = 0.f;
#pragma unroll
    for (int i = 0; i < 7; i++) { a[i] = expf(a[i] - m); sum += a[i]; }
    const float inv = 1.0f / sum;
#pragma unroll
    for (int i = 0; i < 7; i++) a[i] *= inv;

    const float* hb = h + (size_t)b * Tn * Dn;
#pragma unroll
    for (int j = 0; j < 8; j++) {
        const int dbase = (lane + 32 * j) * 4;
        float4 accv = make_float4(0.f, 0.f, 0.f, 0.f);
#pragma unroll
        for (int i = 0; i < 7; i++) {
            const int sc = min(max(t - WINn + i, 0), Tn - 1);
            const float4 hv = *(const float4*)(hb + (size_t)sc * Dn + dbase);
            accv.x = fmaf(a[i], hv.x, accv.x);
            accv.y = fmaf(a[i], hv.y, accv.y);
            accv.z = fmaf(a[i], hv.z, accv.z);
            accv.w = fmaf(a[i], hv.w, accv.w);
        }
        *(float4*)&ctx_sh[w * Dn + dbase] = accv;
    }
    __syncthreads();

    const int tl = w;
    const int k  = lane;
    const float* crow = ctx_sh + tl * Dn;

    float accl = 0.f;
#pragma unroll 8
    for (int dd = 0; dd < Dn; dd += 4) {
        const float4 cv = *(const float4*)(crow + dd);
        accl = fmaf(cv.x, Wp[(dd + 0) * KLn + k], accl);
        accl = fmaf(cv.y, Wp[(dd + 1) * KLn + k], accl);
        accl = fmaf(cv.z, Wp[(dd + 2) * KLn + k], accl);
        accl = fmaf(cv.w, Wp[(dd + 3) * KLn + k], accl);
    }
    const float logit = accl / tau[0];

    float mm = logit;
#pragma unroll
    for (int off = 16; off; off >>= 1)
        mm = fmaxf(mm, __shfl_xor_sync(0xffffffffu, mm, off));
    const float e = expf(logit - mm);
    float ss = e;
#pragma unroll
    for (int off = 16; off; off >>= 1)
        ss += __shfl_xor_sync(0xffffffffu, ss, off);

    out[((size_t)(b * Tn + t)) * KLn + k] = e / ss;
}

// ----------------------------------------------------------------------------
// Launch
// ----------------------------------------------------------------------------
extern "C" void kernel_launch(void* const* d_in, const int* in_sizes, int n_in,
                              void* d_out, int out_size)
{
    const float* h   = (const float*)d_in[0];
    const float* tau = (const float*)d_in[1];
    const float* WQ  = (const float*)d_in[2];
    const float* WK  = (const float*)d_in[3];
    const float* Wp  = (const float*)d_in[4];
    float* out = (float*)d_out;

    convert_x_kernel<<<(Mtot * Dn / 4) / 256, 256>>>(h);
    convert_w_kernel<<<(512 * KTOT) / 256, 256>>>(WQ, WK);

    dim3 g1(512 / BN, Mtot / BM);      // (4, 128)
    qk_mma_kernel<<<g1, 256>>>();

    dim3 g2(Tn / 8, Bn);
    ctx_proj_kernel<<<g2, 256>>>(h, tau, Wp, out);
}

// round 6
// speedup vs baseline: 2.1113x; 1.2092x over previous
#include <cuda_runtime.h>
#include <cuda_bf16.h>
#include <math.h>
#include <stdint.h>

// Problem constants
#define Bn    8
#define Tn    2048
#define Dn    1024
#define DSn   256
#define KLn   32
#define WINn  3
#define Mtot  (Bn * Tn)      // 16384
// SCALE = sqrt(DS) = 16

// Scratch
__device__ float g_Q[Mtot * DSn];                    // 16 MB
__device__ float g_K[Mtot * DSn];                    // 16 MB
__device__ __nv_bfloat16 g_Xhi[Mtot * Dn];           // 32 MB
__device__ __nv_bfloat16 g_Xlo[Mtot * Dn];           // 32 MB
#define KTOT 3072
__device__ __nv_bfloat16 g_Wsp[512 * KTOT];          // 3 MB: [n][k''], k''=[hi|lo|hi]

__device__ __forceinline__ uint32_t smem_u32(const void* p) {
    uint32_t a;
    asm("{ .reg .u64 t; cvta.to.shared.u64 t, %1; cvt.u32.u64 %0, t; }" : "=r"(a) : "l"(p));
    return a;
}
__device__ __forceinline__ void cp16(uint32_t dst, const void* src) {
    asm volatile("cp.async.cg.shared.global [%0], [%1], 16;" :: "r"(dst), "l"(src));
}
#define CP_COMMIT() asm volatile("cp.async.commit_group;" ::: "memory")
#define CP_WAIT(n)  asm volatile("cp.async.wait_group %0;" :: "n"(n) : "memory")

// ---------------------------------------------------------------------------
// Convert X (fp32) -> bf16 hi/lo
// ---------------------------------------------------------------------------
__global__ void convert_x_kernel(const float* __restrict__ X) {
    int idx = blockIdx.x * blockDim.x + threadIdx.x;     // float4 index
    float4 v = *(const float4*)(X + (size_t)idx * 4);
    __nv_bfloat16 hx = __float2bfloat16(v.x);
    __nv_bfloat16 hy = __float2bfloat16(v.y);
    __nv_bfloat16 hz = __float2bfloat16(v.z);
    __nv_bfloat16 hw = __float2bfloat16(v.w);
    __nv_bfloat162 hp0(hx, hy), hp1(hz, hw);
    __nv_bfloat162 lp0(__float2bfloat16(v.x - __bfloat162float(hx)),
                       __float2bfloat16(v.y - __bfloat162float(hy)));
    __nv_bfloat162 lp1(__float2bfloat16(v.z - __bfloat162float(hz)),
                       __float2bfloat16(v.w - __bfloat162float(hw)));
    *(uint2*)(g_Xhi + (size_t)idx * 4) = make_uint2(*(uint32_t*)&hp0, *(uint32_t*)&hp1);
    *(uint2*)(g_Xlo + (size_t)idx * 4) = make_uint2(*(uint32_t*)&lp0, *(uint32_t*)&lp1);
}

// ---------------------------------------------------------------------------
// Build B'' = [Whi | Wlo | Whi] transposed to [n][k''] (n<256: WQ, else WK)
// ---------------------------------------------------------------------------
__global__ void convert_w_kernel(const float* __restrict__ WQ, const float* __restrict__ WK) {
    int idx = blockIdx.x * blockDim.x + threadIdx.x;     // 0 .. 512*3072-1
    int n  = idx / KTOT;
    int kk = idx - n * KTOT;
    int reg = kk >> 10;            // 0:hi 1:lo 2:hi
    int k   = kk & 1023;
    float x = (n < 256) ? WQ[k * 256 + n] : WK[k * 256 + (n - 256)];
    __nv_bfloat16 hi = __float2bfloat16(x);
    __nv_bfloat16 outv = (reg == 1) ? __float2bfloat16(x - __bfloat162float(hi)) : hi;
    g_Wsp[idx] = outv;
}

// ---------------------------------------------------------------------------
// bf16 mma.sync GEMM with 2-stage cp.async pipeline.
// [Q|K](16384 x 512) over K''=3072. CTA tile 128x128, BK=64, 8 warps (2x4).
// ---------------------------------------------------------------------------
#define BM 128
#define BN 128
#define BK 64
#define PAD 8
#define LDS_A (BK + PAD)          // 72 bf16 = 144 B row stride
#define TILE_E (BM * LDS_A)       // bf16 elems per A/B stage
#define STG_B  (TILE_E * 2)       // bytes per stage
#define NIT    (KTOT / BK)        // 48
#define SMEM_GEMM (4 * TILE_E * 2)  // 73728 B

__global__ __launch_bounds__(256, 2)
void qk_mma_kernel() {
    extern __shared__ __nv_bfloat16 smg[];
    __nv_bfloat16* As = smg;                 // [2][TILE_E]
    __nv_bfloat16* Bs = smg + 2 * TILE_E;    // [2][TILE_E]

    const int tid  = threadIdx.x;
    const int wid  = tid >> 5;
    const int lane = tid & 31;
    const int wm = wid & 1;
    const int wn = wid >> 1;
    const int mbase = wm * 64;
    const int nbase = wn * 32;
    const int mtile = blockIdx.y * BM;
    const int ntile = blockIdx.x * BN;

    const int g = lane >> 3;
    const int r = lane & 7;

    float d[4][4][4];
#pragma unroll
    for (int i = 0; i < 4; i++)
#pragma unroll
        for (int j = 0; j < 4; j++)
#pragma unroll
            for (int q = 0; q < 4; q++) d[i][j][q] = 0.f;

    const uint32_t as_base = smem_u32(As);
    const uint32_t bs_base = smem_u32(Bs);

    // load map (per thread: 4 A-chunks + 4 B-chunks of 16B)
    const int lrow[4] = { (0 * 256 + tid) >> 3, (1 * 256 + tid) >> 3,
                          (2 * 256 + tid) >> 3, (3 * 256 + tid) >> 3 };
    const int lc8 = (tid & 7) * 8;

    auto issue_loads = [&](int it, int s) {
        const int kb = it * BK;
        const __nv_bfloat16* Asrc = (kb < 2048) ? g_Xhi : g_Xlo;
        const int ksrc = kb & 1023;
#pragma unroll
        for (int i = 0; i < 4; i++) {
            int row = lrow[i];
            cp16(as_base + (uint32_t)(s * TILE_E + row * LDS_A + lc8) * 2u,
                 Asrc + (size_t)(mtile + row) * Dn + ksrc + lc8);
        }
#pragma unroll
        for (int i = 0; i < 4; i++) {
            int row = lrow[i];
            cp16(bs_base + (uint32_t)(s * TILE_E + row * LDS_A + lc8) * 2u,
                 g_Wsp + (size_t)(ntile + row) * KTOT + kb + lc8);
        }
        CP_COMMIT();
    };

    issue_loads(0, 0);

    for (int it = 0; it < NIT; it++) {
        const int cur = it & 1;
        if (it + 1 < NIT) issue_loads(it + 1, cur ^ 1);
        if (it + 1 < NIT) { CP_WAIT(1); } else { CP_WAIT(0); }
        __syncthreads();

        const uint32_t as_s = as_base + (uint32_t)cur * STG_B;
        const uint32_t bs_s = bs_base + (uint32_t)cur * STG_B;

#pragma unroll
        for (int ks = 0; ks < BK / 16; ks++) {
            const int k0 = ks * 16;
            uint32_t a[4][4];
#pragma unroll
            for (int mf = 0; mf < 4; mf++) {
                int row = mbase + mf * 16 + (g & 1) * 8 + r;
                int col = k0 + (g >> 1) * 8;
                uint32_t addr = as_s + (uint32_t)(row * LDS_A + col) * 2u;
                asm volatile("ldmatrix.sync.aligned.m8n8.x4.shared.b16 {%0,%1,%2,%3}, [%4];"
                             : "=r"(a[mf][0]), "=r"(a[mf][1]), "=r"(a[mf][2]), "=r"(a[mf][3])
                             : "r"(addr));
            }
            uint32_t b[4][2];
#pragma unroll
            for (int nh = 0; nh < 2; nh++) {
                int row = nbase + nh * 16 + (g >> 1) * 8 + r;
                int col = k0 + (g & 1) * 8;
                uint32_t addr = bs_s + (uint32_t)(row * LDS_A + col) * 2u;
                uint32_t t0, t1, t2, t3;
                asm volatile("ldmatrix.sync.aligned.m8n8.x4.shared.b16 {%0,%1,%2,%3}, [%4];"
                             : "=r"(t0), "=r"(t1), "=r"(t2), "=r"(t3) : "r"(addr));
                b[nh * 2 + 0][0] = t0; b[nh * 2 + 0][1] = t1;
                b[nh * 2 + 1][0] = t2; b[nh * 2 + 1][1] = t3;
            }
#pragma unroll
            for (int mf = 0; mf < 4; mf++)
#pragma unroll
                for (int nf = 0; nf < 4; nf++) {
                    asm volatile(
                        "mma.sync.aligned.m16n8k16.row.col.f32.bf16.bf16.f32 "
                        "{%0,%1,%2,%3}, {%4,%5,%6,%7}, {%8,%9}, {%0,%1,%2,%3};"
                        : "+f"(d[mf][nf][0]), "+f"(d[mf][nf][1]),
                          "+f"(d[mf][nf][2]), "+f"(d[mf][nf][3])
                        : "r"(a[mf][0]), "r"(a[mf][1]), "r"(a[mf][2]), "r"(a[mf][3]),
                          "r"(b[nf][0]), "r"(b[nf][1]));
                }
        }
        __syncthreads();
    }

    float* dst = (ntile < 256) ? g_Q : g_K;
    const int ncol0 = (ntile & 255) + nbase;
#pragma unroll
    for (int mf = 0; mf < 4; mf++) {
#pragma unroll
        for (int nf = 0; nf < 4; nf++) {
            int row = mtile + mbase + mf * 16 + (lane >> 2);
            int col = ncol0 + nf * 8 + (lane & 3) * 2;
            *(float2*)(dst + (size_t)row * DSn + col) =
                make_float2(d[mf][nf][0], d[mf][nf][1]);
            *(float2*)(dst + (size_t)(row + 8) * DSn + col) =
                make_float2(d[mf][nf][2], d[mf][nf][3]);
        }
    }
}

// ----------------------------------------------------------------------------
// Stage 2: banded attention + ctx + cooperative projection + softmax.
// 8 warps per block, 8 t's. Projection: warp w owns d-slice [w*128, w*128+128),
// accumulates partial logits for ALL 8 t's, then cross-warp smem reduction.
// ----------------------------------------------------------------------------
__global__ __launch_bounds__(256)
void ctx_proj_kernel(const float* __restrict__ h,
                     const float* __restrict__ tau,
                     const float* __restrict__ Wp,
                     float* __restrict__ out)
{
    __shared__ float ctx_sh[8 * Dn];        // 32 KB
    __shared__ float part[8][8][KLn];       // 8 KB: [warp][t][k]

    const int b    = blockIdx.y;
    const int t0   = blockIdx.x * 8;
    const int w    = threadIdx.x >> 5;
    const int lane = threadIdx.x & 31;
    const int t    = t0 + w;

    // ---- banded scores ----
    const float* Qt = g_Q + ((size_t)(b * Tn + t)) * DSn + lane * 8;
    const float4 q0 = *(const float4*)(Qt);
    const float4 q1 = *(const float4*)(Qt + 4);

    float a[7];
#pragma unroll
    for (int i = 0; i < 7; i++) {
        const int s  = t - WINn + i;
        const int sc = min(max(s, 0), Tn - 1);
        const float* Ks = g_K + ((size_t)(b * Tn + sc)) * DSn + lane * 8;
        const float4 k0 = *(const float4*)(Ks);
        const float4 k1 = *(const float4*)(Ks + 4);
        float p = q0.x*k0.x + q0.y*k0.y + q0.z*k0.z + q0.w*k0.w
                + q1.x*k1.x + q1.y*k1.y + q1.z*k1.z + q1.w*k1.w;
#pragma unroll
        for (int off = 16; off; off >>= 1)
            p += __shfl_xor_sync(0xffffffffu, p, off);
        a[i] = (s >= 0 && s < Tn) ? p * (1.0f / 16.0f) : -INFINITY;
    }

    float m = a[0];
#pragma unroll
    for (int i = 1; i < 7; i++) m = fmaxf(m, a[i]);
    float sum = 0.f;
#pragma unroll
    for (int i = 0; i < 7; i++) { a[i] = expf(a[i] - m); sum += a[i]; }
    const float inv = 1.0f / sum;
#pragma unroll
    for (int i = 0; i < 7; i++) a[i] *= inv;

    // ---- ctx[t] = sum_s a_s * h[b][s][:] -> smem ----
    const float* hb = h + (size_t)b * Tn * Dn;
#pragma unroll
    for (int j = 0; j < 8; j++) {
        const int dbase = (lane + 32 * j) * 4;
        float4 accv = make_float4(0.f, 0.f, 0.f, 0.f);
#pragma unroll
        for (int i = 0; i < 7; i++) {
            const int sc = min(max(t - WINn + i, 0), Tn - 1);
            const float4 hv = *(const float4*)(hb + (size_t)sc * Dn + dbase);
            accv.x = fmaf(a[i], hv.x, accv.x);
            accv.y = fmaf(a[i], hv.y, accv.y);
            accv.z = fmaf(a[i], hv.z, accv.z);
            accv.w = fmaf(a[i], hv.w, accv.w);
        }
        *(float4*)&ctx_sh[w * Dn + dbase] = accv;
    }
    __syncthreads();

    // ---- cooperative projection: warp w covers d in [w*128, w*128+128) ----
    {
        const int d0 = w * 128;
        float acc[8];
#pragma unroll
        for (int tt = 0; tt < 8; tt++) acc[tt] = 0.f;

#pragma unroll 4
        for (int ds = 0; ds < 128; ds += 4) {
            const int dd = d0 + ds;
            const float w0 = Wp[(dd + 0) * KLn + lane];
            const float w1 = Wp[(dd + 1) * KLn + lane];
            const float w2 = Wp[(dd + 2) * KLn + lane];
            const float w3 = Wp[(dd + 3) * KLn + lane];
#pragma unroll
            for (int tt = 0; tt < 8; tt++) {
                const float4 cv = *(const float4*)&ctx_sh[tt * Dn + dd];
                float s0 = fmaf(cv.x, w0, fmaf(cv.y, w1, 0.f));
                float s1 = fmaf(cv.z, w2, fmaf(cv.w, w3, 0.f));
                acc[tt] += s0 + s1;
            }
        }
#pragma unroll
        for (int tt = 0; tt < 8; tt++) part[w][tt][lane] = acc[tt];
    }
    __syncthreads();

    // ---- warp w reduces t = t0 + w, softmax over k = lane ----
    float s = 0.f;
#pragma unroll
    for (int ww = 0; ww < 8; ww++) s += part[ww][w][lane];
    const float logit = s / tau[0];

    float mm = logit;
#pragma unroll
    for (int off = 16; off; off >>= 1)
        mm = fmaxf(mm, __shfl_xor_sync(0xffffffffu, mm, off));
    const float e = expf(logit - mm);
    float ss = e;
#pragma unroll
    for (int off = 16; off; off >>= 1)
        ss += __shfl_xor_sync(0xffffffffu, ss, off);

    out[((size_t)(b * Tn + t)) * KLn + lane] = e / ss;
}

// ----------------------------------------------------------------------------
// Launch
// ----------------------------------------------------------------------------
extern "C" void kernel_launch(void* const* d_in, const int* in_sizes, int n_in,
                              void* d_out, int out_size)
{
    const float* h   = (const float*)d_in[0];
    const float* tau = (const float*)d_in[1];
    const float* WQ  = (const float*)d_in[2];
    const float* WK  = (const float*)d_in[3];
    const float* Wp  = (const float*)d_in[4];
    float* out = (float*)d_out;

    cudaFuncSetAttribute(qk_mma_kernel,
                         cudaFuncAttributeMaxDynamicSharedMemorySize, SMEM_GEMM);

    convert_x_kernel<<<(Mtot * Dn / 4) / 256, 256>>>(h);
    convert_w_kernel<<<(512 * KTOT) / 256, 256>>>(WQ, WK);

    dim3 g1(512 / BN, Mtot / BM);      // (4, 128)
    qk_mma_kernel<<<g1, 256, SMEM_GEMM>>>();

    dim3 g2(Tn / 8, Bn);
    ctx_proj_kernel<<<g2, 256>>>(h, tau, Wp, out);
}

// round 7
// speedup vs baseline: 2.3620x; 1.1188x over previous
#include <cuda_runtime.h>
#include <cuda_bf16.h>
#include <math.h>
#include <stdint.h>

// Problem constants
#define Bn    8
#define Tn    2048
#define Dn    1024
#define DSn   256
#define KLn   32
#define WINn  3
#define Mtot  (Bn * Tn)      // 16384
// SCALE = sqrt(DS) = 16

// Scratch
__device__ float g_Q[Mtot * DSn];                    // 16 MB
__device__ float g_K[Mtot * DSn];                    // 16 MB
__device__ __nv_bfloat16 g_Xhi[Mtot * Dn];           // 32 MB
__device__ __nv_bfloat16 g_Xlo[Mtot * Dn];           // 32 MB
#define KTOT 3072
__device__ __nv_bfloat16 g_Wsp[512 * KTOT];          // 3 MB: [n][k''], k''=[hi|lo|hi]

__device__ __forceinline__ uint32_t smem_u32(const void* p) {
    uint32_t a;
    asm("{ .reg .u64 t; cvta.to.shared.u64 t, %1; cvt.u32.u64 %0, t; }" : "=r"(a) : "l"(p));
    return a;
}
__device__ __forceinline__ void cp16(uint32_t dst, const void* src) {
    asm volatile("cp.async.cg.shared.global [%0], [%1], 16;" :: "r"(dst), "l"(src));
}
#define CP_COMMIT() asm volatile("cp.async.commit_group;" ::: "memory")
#define CP_WAIT(n)  asm volatile("cp.async.wait_group %0;" :: "n"(n) : "memory")

// ---------------------------------------------------------------------------
// Convert X (fp32) -> bf16 hi/lo
// ---------------------------------------------------------------------------
__global__ void convert_x_kernel(const float* __restrict__ X) {
    int idx = blockIdx.x * blockDim.x + threadIdx.x;     // float4 index
    float4 v = *(const float4*)(X + (size_t)idx * 4);
    __nv_bfloat16 hx = __float2bfloat16(v.x);
    __nv_bfloat16 hy = __float2bfloat16(v.y);
    __nv_bfloat16 hz = __float2bfloat16(v.z);
    __nv_bfloat16 hw = __float2bfloat16(v.w);
    __nv_bfloat162 hp0(hx, hy), hp1(hz, hw);
    __nv_bfloat162 lp0(__float2bfloat16(v.x - __bfloat162float(hx)),
                       __float2bfloat16(v.y - __bfloat162float(hy)));
    __nv_bfloat162 lp1(__float2bfloat16(v.z - __bfloat162float(hz)),
                       __float2bfloat16(v.w - __bfloat162float(hw)));
    *(uint2*)(g_Xhi + (size_t)idx * 4) = make_uint2(*(uint32_t*)&hp0, *(uint32_t*)&hp1);
    *(uint2*)(g_Xlo + (size_t)idx * 4) = make_uint2(*(uint32_t*)&lp0, *(uint32_t*)&lp1);
}

// ---------------------------------------------------------------------------
// Build B'' = [Whi | Wlo | Whi] transposed to [n][k''] (n<256: WQ, else WK)
// ---------------------------------------------------------------------------
__global__ void convert_w_kernel(const float* __restrict__ WQ, const float* __restrict__ WK) {
    int idx = blockIdx.x * blockDim.x + threadIdx.x;     // 0 .. 512*3072-1
    int n  = idx / KTOT;
    int kk = idx - n * KTOT;
    int reg = kk >> 10;            // 0:hi 1:lo 2:hi
    int k   = kk & 1023;
    float x = (n < 256) ? WQ[k * 256 + n] : WK[k * 256 + (n - 256)];
    __nv_bfloat16 hi = __float2bfloat16(x);
    __nv_bfloat16 outv = (reg == 1) ? __float2bfloat16(x - __bfloat162float(hi)) : hi;
    g_Wsp[idx] = outv;
}

// ---------------------------------------------------------------------------
// bf16 mma.sync GEMM with 3-stage cp.async pipeline.
// [Q|K](16384 x 512) over K''=3072. CTA tile 128x128, BK=64, 8 warps (2x4).
// ---------------------------------------------------------------------------
#define BM 128
#define BN 128
#define BK 64
#define PAD 8
#define LDS_A (BK + PAD)          // 72 bf16 = 144 B row stride
#define TILE_E (BM * LDS_A)       // bf16 elems per A/B stage (9216)
#define STG_B  (TILE_E * 2)       // bytes per stage
#define NIT    (KTOT / BK)        // 48
#define NSTG   3
#define SMEM_GEMM (NSTG * 2 * TILE_E * 2)  // 110592 B

__global__ __launch_bounds__(256, 2)
void qk_mma_kernel() {
    extern __shared__ __nv_bfloat16 smg[];
    __nv_bfloat16* As = smg;                      // [NSTG][TILE_E]
    __nv_bfloat16* Bs = smg + NSTG * TILE_E;      // [NSTG][TILE_E]

    const int tid  = threadIdx.x;
    const int wid  = tid >> 5;
    const int lane = tid & 31;
    const int wm = wid & 1;
    const int wn = wid >> 1;
    const int mbase = wm * 64;
    const int nbase = wn * 32;
    const int mtile = blockIdx.y * BM;
    const int ntile = blockIdx.x * BN;

    const int g = lane >> 3;
    const int r = lane & 7;

    float d[4][4][4];
#pragma unroll
    for (int i = 0; i < 4; i++)
#pragma unroll
        for (int j = 0; j < 4; j++)
#pragma unroll
            for (int q = 0; q < 4; q++) d[i][j][q] = 0.f;

    const uint32_t as_base = smem_u32(As);
    const uint32_t bs_base = smem_u32(Bs);

    const int lrow[4] = { (0 * 256 + tid) >> 3, (1 * 256 + tid) >> 3,
                          (2 * 256 + tid) >> 3, (3 * 256 + tid) >> 3 };
    const int lc8 = (tid & 7) * 8;

    auto issue_loads = [&](int it, int s) {
        const int kb = it * BK;
        const __nv_bfloat16* Asrc = (kb < 2048) ? g_Xhi : g_Xlo;
        const int ksrc = kb & 1023;
#pragma unroll
        for (int i = 0; i < 4; i++) {
            int row = lrow[i];
            cp16(as_base + (uint32_t)(s * TILE_E + row * LDS_A + lc8) * 2u,
                 Asrc + (size_t)(mtile + row) * Dn + ksrc + lc8);
        }
#pragma unroll
        for (int i = 0; i < 4; i++) {
            int row = lrow[i];
            cp16(bs_base + (uint32_t)(s * TILE_E + row * LDS_A + lc8) * 2u,
                 g_Wsp + (size_t)(ntile + row) * KTOT + kb + lc8);
        }
        CP_COMMIT();
    };

    issue_loads(0, 0);
    issue_loads(1, 1);

    for (int it = 0; it < NIT; it++) {
        if (it < NIT - 1) { CP_WAIT(1); } else { CP_WAIT(0); }
        __syncthreads();

        const int cur = it % NSTG;
        const uint32_t as_s = as_base + (uint32_t)cur * STG_B;
        const uint32_t bs_s = bs_base + (uint32_t)cur * STG_B;

#pragma unroll
        for (int ks = 0; ks < BK / 16; ks++) {
            const int k0 = ks * 16;
            uint32_t a[4][4];
#pragma unroll
            for (int mf = 0; mf < 4; mf++) {
                int row = mbase + mf * 16 + (g & 1) * 8 + r;
                int col = k0 + (g >> 1) * 8;
                uint32_t addr = as_s + (uint32_t)(row * LDS_A + col) * 2u;
                asm volatile("ldmatrix.sync.aligned.m8n8.x4.shared.b16 {%0,%1,%2,%3}, [%4];"
                             : "=r"(a[mf][0]), "=r"(a[mf][1]), "=r"(a[mf][2]), "=r"(a[mf][3])
                             : "r"(addr));
            }
            uint32_t b[4][2];
#pragma unroll
            for (int nh = 0; nh < 2; nh++) {
                int row = nbase + nh * 16 + (g >> 1) * 8 + r;
                int col = k0 + (g & 1) * 8;
                uint32_t addr = bs_s + (uint32_t)(row * LDS_A + col) * 2u;
                uint32_t t0, t1, t2, t3;
                asm volatile("ldmatrix.sync.aligned.m8n8.x4.shared.b16 {%0,%1,%2,%3}, [%4];"
                             : "=r"(t0), "=r"(t1), "=r"(t2), "=r"(t3) : "r"(addr));
                b[nh * 2 + 0][0] = t0; b[nh * 2 + 0][1] = t1;
                b[nh * 2 + 1][0] = t2; b[nh * 2 + 1][1] = t3;
            }
#pragma unroll
            for (int mf = 0; mf < 4; mf++)
#pragma unroll
                for (int nf = 0; nf < 4; nf++) {
                    asm volatile(
                        "mma.sync.aligned.m16n8k16.row.col.f32.bf16.bf16.f32 "
                        "{%0,%1,%2,%3}, {%4,%5,%6,%7}, {%8,%9}, {%0,%1,%2,%3};"
                        : "+f"(d[mf][nf][0]), "+f"(d[mf][nf][1]),
                          "+f"(d[mf][nf][2]), "+f"(d[mf][nf][3])
                        : "r"(a[mf][0]), "r"(a[mf][1]), "r"(a[mf][2]), "r"(a[mf][3]),
                          "r"(b[nf][0]), "r"(b[nf][1]));
                }
        }

        if (it + 2 < NIT) issue_loads(it + 2, (it + 2) % NSTG);
    }

    float* dst = (ntile < 256) ? g_Q : g_K;
    const int ncol0 = (ntile & 255) + nbase;
#pragma unroll
    for (int mf = 0; mf < 4; mf++) {
#pragma unroll
        for (int nf = 0; nf < 4; nf++) {
            int row = mtile + mbase + mf * 16 + (lane >> 2);
            int col = ncol0 + nf * 8 + (lane & 3) * 2;
            *(float2*)(dst + (size_t)row * DSn + col) =
                make_float2(d[mf][nf][0], d[mf][nf][1]);
            *(float2*)(dst + (size_t)(row + 8) * DSn + col) =
                make_float2(d[mf][nf][2], d[mf][nf][3]);
        }
    }
}

// ----------------------------------------------------------------------------
// Stage 2: banded attention + d-partitioned ctx + cooperative projection.
// 8 warps, 8 t's per block.
//  Phase 1: warp w computes band softmax weights for t = t0+w -> coef[w][i].
//  Phase 2: warp w owns d-slice [w*128, w*128+128); loads each of the block's
//           14 unique h rows ONCE, accumulates ctx for all 8 t's in registers.
//  Phase 3: cooperative projection (warp w = same d-slice) + cross-warp reduce.
// ----------------------------------------------------------------------------
__global__ __launch_bounds__(256)
void ctx_proj_kernel(const float* __restrict__ h,
                     const float* __restrict__ tau,
                     const float* __restrict__ Wp,
                     float* __restrict__ out)
{
    __shared__ float ctx_sh[8 * Dn];        // 32 KB
    __shared__ float part[8][8][KLn];       // 8 KB
    __shared__ float coef[8][8];            // [tt][i] band weights

    const int b    = blockIdx.y;
    const int t0   = blockIdx.x * 8;
    const int w    = threadIdx.x >> 5;
    const int lane = threadIdx.x & 31;
    const int t    = t0 + w;

    // ---- Phase 1: banded scores + softmax weights for t = t0 + w ----
    {
        const float* Qt = g_Q + ((size_t)(b * Tn + t)) * DSn + lane * 8;
        const float4 q0 = *(const float4*)(Qt);
        const float4 q1 = *(const float4*)(Qt + 4);

        float a[7];
#pragma unroll
        for (int i = 0; i < 7; i++) {
            const int s  = t - WINn + i;
            const int sc = min(max(s, 0), Tn - 1);
            const float* Ks = g_K + ((size_t)(b * Tn + sc)) * DSn + lane * 8;
            const float4 k0 = *(const float4*)(Ks);
            const float4 k1 = *(const float4*)(Ks + 4);
            float p = q0.x*k0.x + q0.y*k0.y + q0.z*k0.z + q0.w*k0.w
                    + q1.x*k1.x + q1.y*k1.y + q1.z*k1.z + q1.w*k1.w;
#pragma unroll
            for (int off = 16; off; off >>= 1)
                p += __shfl_xor_sync(0xffffffffu, p, off);
            a[i] = (s >= 0 && s < Tn) ? p * (1.0f / 16.0f) : -INFINITY;
        }

        float m = a[0];
#pragma unroll
        for (int i = 1; i < 7; i++) m = fmaxf(m, a[i]);
        float sum = 0.f;
#pragma unroll
        for (int i = 0; i < 7; i++) { a[i] = expf(a[i] - m); sum += a[i]; }
        const float inv = 1.0f / sum;
        if (lane < 7) coef[w][lane] = a[lane] * inv;
    }
    __syncthreads();

    // ---- Phase 2: ctx for all 8 t's over d-slice [w*128, w*128+128) ----
    {
        const int d4 = w * 128 + lane * 4;
        const float* hb = h + (size_t)b * Tn * Dn;

        float4 acc[8];
#pragma unroll
        for (int tt = 0; tt < 8; tt++) acc[tt] = make_float4(0.f, 0.f, 0.f, 0.f);

#pragma unroll
        for (int si = 0; si < 14; si++) {
            const int srow = min(max(t0 - WINn + si, 0), Tn - 1);
            const float4 hv = *(const float4*)(hb + (size_t)srow * Dn + d4);
#pragma unroll
            for (int tt = 0; tt < 8; tt++) {
                if (si - tt >= 0 && si - tt <= 6) {          // compile-time pruned
                    const float c = coef[tt][si - tt];       // smem broadcast
                    acc[tt].x = fmaf(c, hv.x, acc[tt].x);
                    acc[tt].y = fmaf(c, hv.y, acc[tt].y);
                    acc[tt].z = fmaf(c, hv.z, acc[tt].z);
                    acc[tt].w = fmaf(c, hv.w, acc[tt].w);
                }
            }
        }
#pragma unroll
        for (int tt = 0; tt < 8; tt++)
            *(float4*)&ctx_sh[tt * Dn + d4] = acc[tt];
    }
    __syncthreads();

    // ---- Phase 3: cooperative projection, warp w covers d in [w*128, +128) ----
    {
        const int d0 = w * 128;
        float acc[8];
#pragma unroll
        for (int tt = 0; tt < 8; tt++) acc[tt] = 0.f;

#pragma unroll 4
        for (int ds = 0; ds < 128; ds += 4) {
            const int dd = d0 + ds;
            const float w0 = Wp[(dd + 0) * KLn + lane];
            const float w1 = Wp[(dd + 1) * KLn + lane];
            const float w2 = Wp[(dd + 2) * KLn + lane];
            const float w3 = Wp[(dd + 3) * KLn + lane];
#pragma unroll
            for (int tt = 0; tt < 8; tt++) {
                const float4 cv = *(const float4*)&ctx_sh[tt * Dn + dd];
                float s0 = fmaf(cv.x, w0, fmaf(cv.y, w1, 0.f));
                float s1 = fmaf(cv.z, w2, fmaf(cv.w, w3, 0.f));
                acc[tt] += s0 + s1;
            }
        }
#pragma unroll
        for (int tt = 0; tt < 8; tt++) part[w][tt][lane] = acc[tt];
    }
    __syncthreads();

    // ---- warp w reduces t = t0 + w, softmax over k = lane ----
    float s = 0.f;
#pragma unroll
    for (int ww = 0; ww < 8; ww++) s += part[ww][w][lane];
    const float logit = s / tau[0];

    float mm = logit;
#pragma unroll
    for (int off = 16; off; off >>= 1)
        mm = fmaxf(mm, __shfl_xor_sync(0xffffffffu, mm, off));
    const float e = expf(logit - mm);
    float ss = e;
#pragma unroll
    for (int off = 16; off; off >>= 1)
        ss += __shfl_xor_sync(0xffffffffu, ss, off);

    out[((size_t)(b * Tn + t)) * KLn + lane] = e / ss;
}

// ----------------------------------------------------------------------------
// Launch
// ----------------------------------------------------------------------------
extern "C" void kernel_launch(void* const* d_in, const int* in_sizes, int n_in,
                              void* d_out, int out_size)
{
    const float* h   = (const float*)d_in[0];
    const float* tau = (const float*)d_in[1];
    const float* WQ  = (const float*)d_in[2];
    const float* WK  = (const float*)d_in[3];
    const float* Wp  = (const float*)d_in[4];
    float* out = (float*)d_out;

    cudaFuncSetAttribute(qk_mma_kernel,
                         cudaFuncAttributeMaxDynamicSharedMemorySize, SMEM_GEMM);

    convert_x_kernel<<<(Mtot * Dn / 4) / 256, 256>>>(h);
    convert_w_kernel<<<(512 * KTOT) / 256, 256>>>(WQ, WK);

    dim3 g1(512 / BN, Mtot / BM);      // (4, 128)
    qk_mma_kernel<<<g1, 256, SMEM_GEMM>>>();

    dim3 g2(Tn / 8, Bn);
    ctx_proj_kernel<<<g2, 256>>>(h, tau, Wp, out);
}